// round 17
// baseline (speedup 1.0000x reference)
#include <cuda_runtime.h>
#include <cuda_bf16.h>
#include <cstdint>

// Problem constants
#define HW_     16384            // H*W
#define CHW_    4194304          // C*H*W
#define NB_     8
#define JD_     32768
#define SPLITK_ 128
#define KCH_    256

// Output chunk offsets (floats): (out_w, x_Qw, x_Kw, x_Vw, gamma, att)
#define OFF_OUTW  0
#define OFF_QW    33554432
#define OFF_KW    67108864
#define OFF_VW    100663296
#define OFF_GAMMA 134217728
#define OFF_ATT   134217729
#define FULL_SIZE 134348801

// ---------------- device-global scratch ------------------------------------
__device__ float g_psum[(size_t)NB_ * SPLITK_ * 16384];  // split-K partials
__device__ float g_sum [(size_t)NB_ * 16384];            // reduced logits
__device__ uint32_t g_whi[3 * 256 * 128];                // W hi bf16x2 [op][m][k/2]
__device__ uint32_t g_wlo[3 * 256 * 128];
__device__ uint32_t g_xh[(size_t)NB_ * CHW_ / 2];        // x^T bf16x2 [b][p][c/2]
__device__ uint32_t g_xl[(size_t)NB_ * CHW_ / 2];
__device__ uint32_t g_qh[(size_t)NB_ * CHW_ / 2];        // Q bf16x2 [b][c][p/2]
__device__ uint32_t g_ql[(size_t)NB_ * CHW_ / 2];
__device__ uint32_t g_kh[(size_t)NB_ * CHW_ / 2];        // K bf16x2 [b][c][p/2]
__device__ uint32_t g_kl[(size_t)NB_ * CHW_ / 2];
__device__ __nv_bfloat16 g_vth[(size_t)NB_ * CHW_];      // Vt bf16 [b][j][i]
__device__ __nv_bfloat16 g_vtl[(size_t)NB_ * CHW_];
__device__ __nv_bfloat16 g_ath[NB_ * 16384];             // att^T bf16 [b][j'][i]
__device__ __nv_bfloat16 g_atl[NB_ * 16384];

// ---------------- helpers ---------------------------------------------------
__device__ __forceinline__ void split2(float x, float y, uint32_t& hi, uint32_t& lo) {
    __nv_bfloat16 hx = __float2bfloat16_rn(x);
    __nv_bfloat16 hy = __float2bfloat16_rn(y);
    __nv_bfloat162 h; h.x = hx; h.y = hy;
    hi = *reinterpret_cast<uint32_t*>(&h);
    __nv_bfloat162 l = __floats2bfloat162_rn(x - __bfloat162float(hx),
                                             y - __bfloat162float(hy));
    lo = *reinterpret_cast<uint32_t*>(&l);
}

__device__ __forceinline__ void mma16816(float* c, const uint32_t a[4],
                                         uint32_t b0, uint32_t b1) {
    asm("mma.sync.aligned.m16n8k16.row.col.f32.bf16.bf16.f32 "
        "{%0,%1,%2,%3}, {%4,%5,%6,%7}, {%8,%9}, {%0,%1,%2,%3};"
        : "+f"(c[0]), "+f"(c[1]), "+f"(c[2]), "+f"(c[3])
        : "r"(a[0]), "r"(a[1]), "r"(a[2]), "r"(a[3]), "r"(b0), "r"(b1));
}

__device__ __forceinline__ void cpa16(uint32_t s, const void* g) {
    asm volatile("cp.async.ca.shared.global [%0], [%1], 16;" :: "r"(s), "l"(g));
}
#define CP_COMMIT() asm volatile("cp.async.commit_group;" ::: "memory")
#define CP_WAIT1()  asm volatile("cp.async.wait_group 1;"  ::: "memory")

__device__ __forceinline__ void ldm_x4(uint32_t* r, uint32_t a) {
    asm volatile("ldmatrix.sync.aligned.m8n8.x4.shared.b16 {%0,%1,%2,%3}, [%4];"
        : "=r"(r[0]), "=r"(r[1]), "=r"(r[2]), "=r"(r[3]) : "r"(a));
}

#define HACC_INIT(acc)                                         \
    float acc[2][8][4];                                        \
    _Pragma("unroll")                                          \
    for (int _i = 0; _i < 2; _i++)                             \
        _Pragma("unroll")                                      \
        for (int _j = 0; _j < 8; _j++)                         \
            _Pragma("unroll")                                  \
            for (int _e = 0; _e < 4; _e++) acc[_i][_j][_e] = 0.f;

// ---------------- cp.async + ldmatrix HMMA core (unchanged from R12/R15) ----
__device__ __forceinline__ void hmma_core(
    const char* gAh, const char* gAl, size_t ldA,
    const char* gBh, const char* gBl, size_t ldB,
    int nChunks, float acc[2][8][4], uint32_t* smraw)
{
    const int tid = threadIdx.x;
    uint32_t sb;
    asm("{ .reg .u64 t; cvta.to.shared.u64 t, %1; cvt.u32.u64 %0, t; }"
        : "=r"(sb) : "l"(smraw));

    const int spl = tid >> 6;
    const int srw = (tid & 63) << 1;
    const char* gb = (spl == 0) ? gAh : (spl == 1) ? gAl : (spl == 2) ? gBh : gBl;
    const size_t ld = (spl < 2) ? ldA : ldB;
    const char* g0 = gb + (size_t)srw * ld;
    const char* g1 = g0 + ld;
    const uint32_t s0 = sb + spl * 6144 + srw * 48;
    const uint32_t s1 = s0 + 48;

#define STG_(ch, bo) do {                                                     \
    const char* _p0 = g0 + (size_t)(ch) * 32;                                 \
    const char* _p1 = g1 + (size_t)(ch) * 32;                                 \
    cpa16(s0 + (bo), _p0); cpa16(s0 + (bo) + 16, _p0 + 16);                   \
    cpa16(s1 + (bo), _p1); cpa16(s1 + (bo) + 16, _p1 + 16); } while (0)

    const int lane = tid & 31, w = tid >> 5;
    const int wm = w & 3, wn = w >> 2;
    const int l7 = lane & 7, lb8 = (lane >> 3) & 1, lb16 = lane >> 4;
    const uint32_t aA0 = sb + (uint32_t)(wm * 32 + l7 + lb8 * 8) * 48 + lb16 * 16;
    const uint32_t aA1 = aA0 + 16 * 48;
    const uint32_t bA  = sb + 12288 + (uint32_t)(wn * 64 + lb16 * 8 + l7) * 48 + lb8 * 16;

    STG_(0, 0); CP_COMMIT();
    STG_(1, 24576); CP_COMMIT();

    #pragma unroll 1
    for (int ch = 0; ch < nChunks; ch++) {
        CP_WAIT1();
        __syncthreads();
        const uint32_t bo = (uint32_t)(ch & 1) * 24576;

        uint32_t aH0[4], aH1[4], aL0[4], aL1[4];
        uint32_t bF[4][4];

        ldm_x4(aH0, aA0 + bo);
        ldm_x4(aH1, aA1 + bo);
        #pragma unroll
        for (int jp = 0; jp < 4; jp++) ldm_x4(bF[jp], bA + bo + jp * 768);

        #pragma unroll
        for (int jp = 0; jp < 4; jp++) {
            mma16816(acc[0][2*jp],   aH0, bF[jp][0], bF[jp][1]);
            mma16816(acc[1][2*jp],   aH1, bF[jp][0], bF[jp][1]);
            mma16816(acc[0][2*jp+1], aH0, bF[jp][2], bF[jp][3]);
            mma16816(acc[1][2*jp+1], aH1, bF[jp][2], bF[jp][3]);
        }

        ldm_x4(aL0, aA0 + bo + 6144);
        ldm_x4(aL1, aA1 + bo + 6144);

        #pragma unroll
        for (int jp = 0; jp < 4; jp++) {
            mma16816(acc[0][2*jp],   aL0, bF[jp][0], bF[jp][1]);
            mma16816(acc[1][2*jp],   aL1, bF[jp][0], bF[jp][1]);
            mma16816(acc[0][2*jp+1], aL0, bF[jp][2], bF[jp][3]);
            mma16816(acc[1][2*jp+1], aL1, bF[jp][2], bF[jp][3]);
        }

        #pragma unroll
        for (int jp = 0; jp < 4; jp++) ldm_x4(bF[jp], bA + bo + jp * 768 + 6144);

        #pragma unroll
        for (int jp = 0; jp < 4; jp++) {
            mma16816(acc[0][2*jp],   aH0, bF[jp][0], bF[jp][1]);
            mma16816(acc[1][2*jp],   aH1, bF[jp][0], bF[jp][1]);
            mma16816(acc[0][2*jp+1], aH0, bF[jp][2], bF[jp][3]);
            mma16816(acc[1][2*jp+1], aH1, bF[jp][2], bF[jp][3]);
        }

        __syncthreads();
        if (ch + 2 < nChunks) STG_(ch + 2, bo);
        CP_COMMIT();
    }
#undef STG_
}

// ---------------- prep kernel: W pre-split ----------------------------------
__global__ void wsplit_kernel(const float* __restrict__ Wq,
                              const float* __restrict__ Wk,
                              const float* __restrict__ Wv)
{
    const int idx = blockIdx.x * 256 + threadIdx.x;   // 98304
    const int op  = idx >> 15;
    const int rem = idx & 32767;
    const float* W = (op == 0) ? Wq : (op == 1) ? Wk : Wv;
    float2 v = *(const float2*)(W + (size_t)rem * 2);
    uint32_t hi, lo;
    split2(v.x, v.y, hi, lo);
    g_whi[idx] = hi;
    g_wlo[idx] = lo;
}

// ---------------- prep kernel: x transpose + pre-split -----------------------
__global__ void xsplit_kernel(const float* __restrict__ x)
{
    __shared__ float t[64][33];
    const int b = blockIdx.z;
    const int p0 = blockIdx.x << 5;
    const int c0 = blockIdx.y << 6;
    const int tx = threadIdx.x, ty = threadIdx.y;
    const float* xb = x + (size_t)b * CHW_;
    #pragma unroll
    for (int r = 0; r < 8; r++) {
        const int cc = ty + r * 8;
        t[cc][tx] = xb[(size_t)(c0 + cc) * HW_ + p0 + tx];
    }
    __syncthreads();
    uint32_t* oh = g_xh + (size_t)b * (CHW_ / 2);
    uint32_t* ol = g_xl + (size_t)b * (CHW_ / 2);
    #pragma unroll
    for (int r = 0; r < 4; r++) {
        const int pp = ty + r * 8;
        uint32_t hi, lo;
        split2(t[2 * tx][pp], t[2 * tx + 1][pp], hi, lo);
        const size_t o = (size_t)(p0 + pp) * 128 + (c0 >> 1) + tx;
        oh[o] = hi;
        ol[o] = lo;
    }
}

// ---------------- kernel 1: QKV conv + bias + ReLU + fused K/V transpose -----
// grid (128, 6, 8): x = n-tile, y = (m-half | op*2), z = batch.
// Q: fp32 natural (if requested) + Q planes natural.
// K: K planes natural (for att) + x_Kw fp32 TRANSPOSED via smem (if requested).
// V: x_Vw fp32 TRANSPOSED (if requested) + Vt bf16 hi/lo planes TRANSPOSED.
__global__ __launch_bounds__(256, 2) void conv_qkv_kernel(
    const float* __restrict__ bq, const float* __restrict__ bk,
    const float* __restrict__ bv,
    float* __restrict__ qw, float* __restrict__ ktw, float* __restrict__ vtw)
{
    __shared__ __align__(16) uint32_t smb[12288];
    const int tid = threadIdx.x, lane = tid & 31, w = tid >> 5;
    const int g = lane >> 2, t4 = lane & 3, wm = w & 3, wn = w >> 2;
    const int b = blockIdx.z, op = blockIdx.y >> 1;
    const int m0 = (blockIdx.y & 1) << 7, n0 = blockIdx.x << 7;

    const uint32_t* Ah = g_whi + op * 32768 + m0 * 128;
    const uint32_t* Al = g_wlo + op * 32768 + m0 * 128;
    const uint32_t* Bh = g_xh + (size_t)b * (CHW_ / 2) + (size_t)n0 * 128;
    const uint32_t* Bl = g_xl + (size_t)b * (CHW_ / 2) + (size_t)n0 * 128;

    HACC_INIT(acc);
    hmma_core((const char*)Ah, (const char*)Al, 512,
              (const char*)Bh, (const char*)Bl, 512, 16, acc, smb);

    const float* bsel = (op == 0) ? bq : (op == 1) ? bk : bv;

    if (op <= 1) {
        // ---- natural-layout writes: Q fp32 (optional) + Q/K planes --------
        float* dstf = (op == 0) ? qw : nullptr;
        if (dstf) dstf += (size_t)b * CHW_;
        uint32_t* ph = ((op == 0) ? g_qh : g_kh) + (size_t)b * (CHW_ / 2);
        uint32_t* pl = ((op == 0) ? g_ql : g_kl) + (size_t)b * (CHW_ / 2);

        #pragma unroll
        for (int im = 0; im < 2; im++) {
            const int mb = m0 + wm * 32 + im * 16;
            const float bb0 = __ldg(bsel + mb + g);
            const float bb1 = __ldg(bsel + mb + g + 8);
            #pragma unroll
            for (int jn = 0; jn < 8; jn++) {
                const int n = n0 + wn * 64 + jn * 8 + t4 * 2;
                float2 v0 = { fmaxf(acc[im][jn][0] + bb0, 0.f),
                              fmaxf(acc[im][jn][1] + bb0, 0.f) };
                float2 v1 = { fmaxf(acc[im][jn][2] + bb1, 0.f),
                              fmaxf(acc[im][jn][3] + bb1, 0.f) };
                const size_t r0 = (size_t)(mb + g) * HW_ + n;
                const size_t r1 = (size_t)(mb + g + 8) * HW_ + n;
                if (dstf) {
                    *(float2*)(dstf + r0) = v0;
                    *(float2*)(dstf + r1) = v1;
                }
                uint32_t hi, lo;
                split2(v0.x, v0.y, hi, lo);
                ph[r0 >> 1] = hi; pl[r0 >> 1] = lo;
                split2(v1.x, v1.y, hi, lo);
                ph[r1 >> 1] = hi; pl[r1 >> 1] = lo;
            }
        }
    }

    // ---- fused transposed epilogue for K (fp32 only) and V (fp32 + planes) --
    const bool wantF = (op == 1) ? (ktw != nullptr) : (vtw != nullptr);
    if (op == 0 || (op == 1 && !wantF)) return;

    float* dstT = (op == 1) ? ktw : vtw;
    if (dstT) dstT += (size_t)b * CHW_;
    const size_t bofs = (size_t)b * CHW_;
    float* smf = (float*)smb;   // 128 x 33 tile

    #pragma unroll 1
    for (int r = 0; r < 4; r++) {
        __syncthreads();
        if (wn == (r >> 1)) {
            const int jbase = (r & 1) * 4;
            #pragma unroll
            for (int jj = 0; jj < 4; jj++) {
                const int jn = jbase + jj;
                const int pr = wn * 64 + jn * 8 + t4 * 2 - r * 32;
                #pragma unroll
                for (int im = 0; im < 2; im++) {
                    const int cb = wm * 32 + im * 16;
                    const float bb0 = __ldg(bsel + m0 + cb + g);
                    const float bb1 = __ldg(bsel + m0 + cb + g + 8);
                    smf[(cb + g    ) * 33 + pr    ] = fmaxf(acc[im][jn][0] + bb0, 0.f);
                    smf[(cb + g    ) * 33 + pr + 1] = fmaxf(acc[im][jn][1] + bb0, 0.f);
                    smf[(cb + g + 8) * 33 + pr    ] = fmaxf(acc[im][jn][2] + bb1, 0.f);
                    smf[(cb + g + 8) * 33 + pr + 1] = fmaxf(acc[im][jn][3] + bb1, 0.f);
                }
            }
        }
        __syncthreads();

        const int row_id = tid >> 2;          // 0..63
        const int par    = row_id >> 5;       // 0,1
        const int p      = row_id & 31;       // 0..31
        const int q      = tid & 3;           // i quarter
        const size_t j   = (size_t)par * 16384 + n0 + r * 32 + p;
        const size_t col = (size_t)(m0 >> 1) + q * 16;

        float f[16];
        #pragma unroll
        for (int t = 0; t < 16; t++)
            f[t] = smf[(2 * (q * 16 + t) + par) * 33 + p];

        if (wantF) {
            float* orow = dstT + j * 128 + col;
            #pragma unroll
            for (int v = 0; v < 4; v++)
                *(float4*)(orow + v * 4) =
                    make_float4(f[v*4], f[v*4+1], f[v*4+2], f[v*4+3]);
        }
        if (op == 2) {
            uint32_t hh[8], ll[8];
            #pragma unroll
            for (int t = 0; t < 8; t++)
                split2(f[2*t], f[2*t+1], hh[t], ll[t]);
            const size_t po = bofs + j * 128 + col;
            *(uint4*)(g_vth + po)     = make_uint4(hh[0], hh[1], hh[2], hh[3]);
            *(uint4*)(g_vth + po + 8) = make_uint4(hh[4], hh[5], hh[6], hh[7]);
            *(uint4*)(g_vtl + po)     = make_uint4(ll[0], ll[1], ll[2], ll[3]);
            *(uint4*)(g_vtl + po + 8) = make_uint4(ll[4], ll[5], ll[6], ll[7]);
        }
    }
}

// ---------------- kernel 3: split-K logit GEMM -------------------------------
__global__ __launch_bounds__(256, 2) void att_gemm_kernel()
{
    __shared__ __align__(16) uint32_t smb[12288];
    const int s = blockIdx.x, b = blockIdx.y;
    const size_t base = (size_t)b * (CHW_ / 2) + (size_t)(s >> 6) * 8192
                      + (size_t)(s & 63) * 128;

    HACC_INIT(acc);
    hmma_core((const char*)(g_qh + base), (const char*)(g_ql + base), 65536,
              (const char*)(g_kh + base), (const char*)(g_kl + base), 65536,
              16, acc, smb);

    float* Cp = g_psum + ((size_t)b * SPLITK_ + s) * 16384;
    const int lane = threadIdx.x & 31, w = threadIdx.x >> 5;
    const int g = lane >> 2, t4 = lane & 3, wm = w & 3, wn = w >> 2;
    #pragma unroll
    for (int im = 0; im < 2; im++) {
        const int mb = wm * 32 + im * 16;
        #pragma unroll
        for (int jn = 0; jn < 8; jn++) {
            const int n = wn * 64 + jn * 8 + t4 * 2;
            *(float2*)(Cp + (size_t)(mb + g    ) * 128 + n) =
                make_float2(acc[im][jn][0], acc[im][jn][1]);
            *(float2*)(Cp + (size_t)(mb + g + 8) * 128 + n) =
                make_float2(acc[im][jn][2], acc[im][jn][3]);
        }
    }
}

// ---------------- kernel 4a: coalesced Kahan reduce over splits --------------
// grid (128 i, 8 b), 128 threads = j' (contiguous => coalesced loads)
__global__ void psum_reduce_kernel()
{
    const int i = blockIdx.x, b = blockIdx.y, j = threadIdx.x;
    const float* p = g_psum + (size_t)b * SPLITK_ * 16384 + (size_t)i * 128 + j;
    float s = 0.f, comp = 0.f;
    for (int t = 0; t < SPLITK_; t++) {
        float y = __fsub_rn(p[(size_t)t * 16384], comp);
        float u = __fadd_rn(s, y);
        comp = __fsub_rn(__fsub_rn(u, s), y);
        s = u;
    }
    g_sum[(size_t)b * 16384 + (size_t)i * 128 + j] = s;
}

// ---------------- kernel 4b: softmax over i (+ att planes) -------------------
// grid (4 j'-tiles, 8 b), 256 threads: lane = j' offset, warp = i group of 16
__global__ void softmax2_kernel(float* __restrict__ attw,
                                float* __restrict__ gmw,
                                const float* __restrict__ gamma)
{
    __shared__ float red[8][32];
    __shared__ float smx[32], sZ[32];
    const int b = blockIdx.y;
    const int lane = threadIdx.x & 31;
    const int w    = threadIdx.x >> 5;
    const int jp   = (blockIdx.x << 5) + lane;

    const float* base = g_sum + (size_t)b * 16384 + (size_t)(w * 16) * 128 + jp;
    float s[16];
    #pragma unroll
    for (int r = 0; r < 16; r++) s[r] = base[(size_t)r * 128];

    float m = s[0];
    #pragma unroll
    for (int r = 1; r < 16; r++) m = fmaxf(m, s[r]);
    red[w][lane] = m;
    __syncthreads();
    if (w == 0) {
        float mm = red[0][lane];
        #pragma unroll
        for (int k = 1; k < 8; k++) mm = fmaxf(mm, red[k][lane]);
        smx[lane] = mm;
    }
    __syncthreads();
    const float mx = smx[lane];

    float e[16], z = 0.f;
    #pragma unroll
    for (int r = 0; r < 16; r++) { e[r] = expf(s[r] - mx); z += e[r]; }
    red[w][lane] = z;
    __syncthreads();
    if (w == 0) {
        float zz = 0.f;
        #pragma unroll
        for (int k = 0; k < 8; k++) zz += red[k][lane];
        sZ[lane] = zz;
    }
    __syncthreads();
    const float zi = 1.f / sZ[lane];

    #pragma unroll
    for (int r = 0; r < 16; r++) {
        const int i = w * 16 + r;
        const float rr = e[r] * zi;
        __nv_bfloat16 h = __float2bfloat16_rn(rr);
        g_ath[(size_t)b * 16384 + (size_t)jp * 128 + i] = h;
        g_atl[(size_t)b * 16384 + (size_t)jp * 128 + i] =
            __float2bfloat16_rn(rr - __bfloat162float(h));
        if (attw) attw[(size_t)b * 16384 + (size_t)i * 128 + jp] = rr;
    }
    if (gmw && b == 0 && blockIdx.x == 0 && threadIdx.x == 0) *gmw = __ldg(gamma);
}

// ---------------- kernel 5: out = Vt @ att, scaled by gamma ------------------
__global__ __launch_bounds__(256, 2) void out_gemm_kernel(
    float* __restrict__ outw, const float* __restrict__ gamma)
{
    __shared__ __align__(16) uint32_t smb[12288];
    const int b  = blockIdx.y;
    const int m0 = blockIdx.x << 7;
    const char* Ah = (const char*)(g_vth + (size_t)b * CHW_ + (size_t)m0 * 128);
    const char* Al = (const char*)(g_vtl + (size_t)b * CHW_ + (size_t)m0 * 128);
    const char* Bh = (const char*)(g_ath + (size_t)b * 16384);
    const char* Bl = (const char*)(g_atl + (size_t)b * 16384);

    HACC_INIT(acc);
    hmma_core(Ah, Al, 256, Bh, Bl, 256, 8, acc, smb);

    const float gsc = __ldg(gamma);
    float* base = outw + (size_t)b * CHW_;
    const int lane = threadIdx.x & 31, w = threadIdx.x >> 5;
    const int g = lane >> 2, t4 = lane & 3, wm = w & 3, wn = w >> 2;
    #pragma unroll
    for (int im = 0; im < 2; im++) {
        const int mb = m0 + wm * 32 + im * 16;
        #pragma unroll
        for (int jn = 0; jn < 8; jn++) {
            const int n = wn * 64 + jn * 8 + t4 * 2;
            *(float2*)(base + (size_t)(mb + g    ) * 128 + n) =
                make_float2(acc[im][jn][0] * gsc, acc[im][jn][1] * gsc);
            *(float2*)(base + (size_t)(mb + g + 8) * 128 + n) =
                make_float2(acc[im][jn][2] * gsc, acc[im][jn][3] * gsc);
        }
    }
}

// ---------------- launch -----------------------------------------------------
extern "C" void kernel_launch(void* const* d_in, const int* in_sizes, int n_in,
                              void* d_out, int out_size)
{
    const float* x  = (const float*)d_in[0];
    const float* Wq = (const float*)d_in[1];
    const float* bq = (const float*)d_in[2];
    const float* Wk = (const float*)d_in[3];
    const float* bk = (const float*)d_in[4];
    const float* Wv = (const float*)d_in[5];
    const float* bv = (const float*)d_in[6];
    const float* gm = (const float*)d_in[7];
    float* out = (float*)d_out;

    const bool full = (out_size >= FULL_SIZE);
    float* outw = out;
    float* qw   = full ? out + OFF_QW    : nullptr;
    float* ktw  = full ? out + OFF_KW    : nullptr;
    float* vtw  = full ? out + OFF_VW    : nullptr;
    float* gmw  = full ? out + OFF_GAMMA : nullptr;
    float* attw = full ? out + OFF_ATT   : nullptr;

    wsplit_kernel<<<384, 256>>>(Wq, Wk, Wv);
    xsplit_kernel<<<dim3(512, 4, 8), dim3(32, 8)>>>(x);
    conv_qkv_kernel<<<dim3(128, 6, 8), 256>>>(bq, bk, bv, qw, ktw, vtw);
    att_gemm_kernel<<<dim3(SPLITK_, 8), 256>>>();
    psum_reduce_kernel<<<dim3(128, 8), 128>>>();
    softmax2_kernel<<<dim3(4, 8), 256>>>(attw, gmw, gm);
    out_gemm_kernel<<<dim3(256, 8), 256>>>(outw, gm);
}